// round 4
// baseline (speedup 1.0000x reference)
#include <cuda_runtime.h>
#include <cstdint>

// PEPS 6x6, D=3, B=16 — both half-contractions in ONE 512-thread CTA.
// Warps 0-7: top half (rows 0-2 downward). Warps 8-15: bottom half
// (rows 5-3 upward, u<->d swapped). Each half: boundary state over 729
// column-bond groups x h (float4/group, h in xyz), 243 workers x 3 o-groups,
// IN-PLACE update (worker's read set == write set). Final amplitude =
// intra-CTA dot of the two 729-vectors at the middle cut. Grid = 16 configs.

#define NTT 512
#define SPAD 2916            // 729 groups * 4 floats
#define ATF 108              // padded floats per site tensor [o][hp'][a][4]

__device__ __forceinline__ float dot3(float4 a, float4 b) {
    return a.x * b.x + a.y * b.y + a.z * b.z;
}

__global__ __launch_bounds__(NTT, 1)
void peps_fused_kernel(const int* __restrict__ xcfg,
                       const float* __restrict__ T,
                       float* __restrict__ out) {
    __shared__ float S[2][SPAD];          // per-half state (in-place)
    __shared__ float At[2][18 * ATF];     // per-half padded site tensors
    __shared__ int   spins[36];
    __shared__ int   sOff[36];
    __shared__ float red[16];

    const int t    = threadIdx.x;
    const int b    = blockIdx.x;
    const int half = t >> 8;              // 0 = top, 1 = bottom
    const int lt   = t & 255;

    if (t < 36) spins[t] = xcfg[b * 36 + t];
    __syncthreads();
    if (t < 36) {
        int xx = t / 6, yy = t % 6;
        int p  = spins[t];
        int pu = (xx > 0) ? spins[t - 6] : 0;
        int pd = (xx < 5) ? spins[t + 6] : 0;
        int pl = (yy > 0) ? spins[t - 1] : 0;
        int pr = (yy < 5) ? spins[t + 1] : 0;
        sOff[t] = (((p * 2 + pu) * 2 + pd) * 2 + pl) * 2 + pr;
    }
    for (int i = t; i < 2 * SPAD; i += NTT) (&S[0][0])[i] = 0.0f;
    __syncthreads();

    // Gather padded site tensors for both halves.
    // Layout At[hh][s][o][hp'][a][lane=h_left(4)]:
    //   top:    T site (s/6, s%6),    u=a(contracted), d=o(output)
    //   bottom: T site (5-s/6, s%6),  u=o, d=a
    for (int i = t; i < 2 * 18 * ATF; i += NTT) {
        int hh = i / (18 * ATF);
        int j  = i - hh * (18 * ATF);
        int s  = j / ATF, r = j - s * ATF;
        int o  = r / 36;  r -= o * 36;
        int hp = r / 12;  r -= hp * 12;
        int a  = r >> 2,  h = r & 3;
        float v = 0.0f;
        if (h < 3) {
            int x = hh ? 5 - s / 6 : s / 6;
            int y = s % 6;
            int u = hh ? o : a;
            int d = hh ? a : o;
            int site = x * 6 + y;
            v = T[site * 2592 + (((u * 3 + d) * 3 + h) * 3 + hp) * 32 + sOff[site]];
        }
        At[hh][j] = v;
    }
    __syncthreads();

    // Init = state after first site (y=0): digit c0 = o, lane = hp'
    // value = A[site0][o][hp'][a=0][h_left=0]
    if (t < 18) {
        int hh = t / 9, k = t - hh * 9;
        int o = k / 3, hp = k - 3 * o;
        S[hh][(o * 243) * 4 + hp] = At[hh][o * 36 + hp * 12];
    }
    __syncthreads();

    float4* C = (float4*)S[half];
    const float4* Atv = (const float4*)At[half];

#define STEP(SITE, S3, TRANS) { \
    if (lt < 243) { \
        int hi = lt / (S3); \
        int lo = lt - hi * (S3); \
        int base = hi * (3 * (S3)) + lo; \
        float4 c0 = C[base]; \
        float4 c1 = C[base + (S3)]; \
        float4 c2 = C[base + 2 * (S3)]; \
        _Pragma("unroll") \
        for (int o_ = 0; o_ < 3; ++o_) { \
            const float4* Av = Atv + (SITE) * 27 + o_ * 9; \
            float r0, r1, r2; \
            if (TRANS) { \
                r0 = c0.x * Av[0].x + c1.x * Av[1].x + c2.x * Av[2].x; \
                r1 = c0.x * Av[3].x + c1.x * Av[4].x + c2.x * Av[5].x; \
                r2 = c0.x * Av[6].x + c1.x * Av[7].x + c2.x * Av[8].x; \
            } else { \
                r0 = dot3(c0, Av[0]) + dot3(c1, Av[1]) + dot3(c2, Av[2]); \
                r1 = dot3(c0, Av[3]) + dot3(c1, Av[4]) + dot3(c2, Av[5]); \
                r2 = dot3(c0, Av[6]) + dot3(c1, Av[7]) + dot3(c2, Av[8]); \
            } \
            C[base + o_ * (S3)] = make_float4(r0, r1, r2, 0.0f); \
        } \
    } \
    __syncthreads(); \
}

    // row 0 (site 0 folded into init): digit strides 3^(5-y)
    STEP(1, 81, false)
    STEP(2, 27, false)
    STEP(3, 9, false)
    STEP(4, 3, false)
    STEP(5, 1, false)
    // row 1 (transition at y=0: project prev h' -> 0, new l = 0)
    STEP(6, 243, true)
    STEP(7, 81, false)
    STEP(8, 27, false)
    STEP(9, 9, false)
    STEP(10, 3, false)
    STEP(11, 1, false)
    // row 2
    STEP(12, 243, true)
    STEP(13, 81, false)
    STEP(14, 27, false)
    STEP(15, 9, false)
    STEP(16, 3, false)
    STEP(17, 1, false)
#undef STEP

    // amplitude = sum_g top[g, h=0] * bottom[g, h=0]
    float s = 0.0f;
    for (int g = t; g < 729; g += NTT) s += S[0][4 * g] * S[1][4 * g];
    #pragma unroll
    for (int o = 16; o; o >>= 1) s += __shfl_xor_sync(0xFFFFFFFFu, s, o);
    if ((t & 31) == 0) red[t >> 5] = s;
    __syncthreads();
    if (t == 0) {
        float tt = 0.0f;
        #pragma unroll
        for (int w = 0; w < 16; ++w) tt += red[w];
        out[b] = tt;
    }
}

extern "C" void kernel_launch(void* const* d_in, const int* in_sizes, int n_in,
                              void* d_out, int out_size) {
    const int*   xcfg = nullptr;
    const float* T    = nullptr;
    for (int i = 0; i < n_in; ++i) {
        if (in_sizes[i] == 576) xcfg = (const int*)d_in[i];
        else                    T    = (const float*)d_in[i];
    }
    float* out = (float*)d_out;
    peps_fused_kernel<<<16, NTT>>>(xcfg, T, out);
}

// round 5
// speedup vs baseline: 1.2738x; 1.2738x over previous
#include <cuda_runtime.h>
#include <cstdint>

// PEPS 6x6, D=3, B=16 — cluster-sharded bidirectional contraction.
// Cluster of 6 CTAs per config: ranks 0-2 = top half (rows 0-2), sharding the
// boundary state by digit c0 (c0 = rank%3); ranks 3-5 = bottom half (rows 5-3,
// u<->d swapped), same sharding. Each CTA holds 243 groups (digits c1..c5)
// x h (float4). 15/17 steps are shard-local; the two row-transition steps
// (y=0) contract c0 across shards via 2 remote DSMEM scalar reads/thread.
// Final: top shard k dots its 243 groups against bottom shard k (DSMEM),
// partials pushed to rank 0. Grid = 96 CTAs.

#define NTH 256
#define NG  243              // groups per shard
#define ATF 108              // padded floats per site tensor [o][hp][a][4:h]

__device__ __forceinline__ float dot3(float4 a, float4 b) {
    return a.x * b.x + a.y * b.y + a.z * b.z;
}

__device__ __forceinline__ uint32_t smem_u32(const void* p) {
    uint32_t a;
    asm("{ .reg .u64 t; cvta.to.shared.u64 t, %1; cvt.u32.u64 %0, t; }"
        : "=r"(a) : "l"(p));
    return a;
}

__device__ __forceinline__ float ld_cluster_f32(uint32_t laddr, uint32_t rank) {
    uint32_t r; float v;
    asm volatile("mapa.shared::cluster.u32 %0, %1, %2;" : "=r"(r) : "r"(laddr), "r"(rank));
    asm volatile("ld.shared::cluster.f32 %0, [%1];" : "=f"(v) : "r"(r) : "memory");
    return v;
}

__device__ __forceinline__ void st_cluster_f32(uint32_t laddr, uint32_t rank, float v) {
    uint32_t r;
    asm volatile("mapa.shared::cluster.u32 %0, %1, %2;" : "=r"(r) : "r"(laddr), "r"(rank));
    asm volatile("st.shared::cluster.f32 [%0], %1;" :: "r"(r), "f"(v) : "memory");
}

#define CLUSTER_BAR() do { \
    asm volatile("barrier.cluster.arrive.aligned;" ::: "memory"); \
    asm volatile("barrier.cluster.wait.aligned;"   ::: "memory"); \
} while (0)

__global__ __launch_bounds__(NTH, 1) __cluster_dims__(6, 1, 1)
void peps_cluster_kernel(const int* __restrict__ xcfg,
                         const float* __restrict__ T,
                         float* __restrict__ out) {
    __shared__ float4 S0[NG];
    __shared__ float4 S1[NG];
    __shared__ float  At[18 * ATF];
    __shared__ int    spins[36];
    __shared__ int    sOff[36];
    __shared__ float  wred[8];
    __shared__ float  cred[3];

    const int t = threadIdx.x;
    const int b = blockIdx.x / 6;
    uint32_t rank;
    asm("mov.u32 %0, %%cluster_ctarank;" : "=r"(rank));
    const int half = (int)rank / 3;        // 0 = top, 1 = bottom
    const int part = (int)rank % 3;        // my c0 shard
    const uint32_t base_rank = half * 3;

    if (t < 36) spins[t] = xcfg[b * 36 + t];
    __syncthreads();
    if (t < 36) {
        int xx = t / 6, yy = t % 6;
        int p  = spins[t];
        int pu = (xx > 0) ? spins[t - 6] : 0;
        int pd = (xx < 5) ? spins[t + 6] : 0;
        int pl = (yy > 0) ? spins[t - 1] : 0;
        int pr = (yy < 5) ? spins[t + 1] : 0;
        sOff[t] = (((p * 2 + pu) * 2 + pd) * 2 + pl) * 2 + pr;
    }
    __syncthreads();

    // Gather my half's padded site tensors: At[s][o][hp][a][lane=h].
    //   top:    T site (s/6, s%6),    u=a (contracted), d=o (output)
    //   bottom: T site (5-s/6, s%6),  u=o, d=a
    for (int i = t; i < 18 * ATF; i += NTH) {
        int s = i / ATF, r = i - s * ATF;
        int o  = r / 36;  r -= o * 36;
        int hp = r / 12;  r -= hp * 12;
        int a  = r >> 2,  h = r & 3;
        float v = 0.0f;
        if (h < 3) {
            int x = half ? 5 - s / 6 : s / 6;
            int y = s % 6;
            int u = half ? o : a;
            int d = half ? a : o;
            int site = x * 6 + y;
            v = T[site * 2592 + (((u * 3 + d) * 3 + h) * 3 + hp) * 32 + sOff[site]];
        }
        At[i] = v;
    }
    __syncthreads();

    // Init = state after site 0 (y=0): my shard's c0 = part; only group 0
    // (c1..c5 = 0) nonzero; value = A0[o=part][hp][a=0][h=0].
    if (t < NG) {
        S0[t] = (t == 0)
            ? make_float4(At[part * 36], At[part * 36 + 12], At[part * 36 + 24], 0.0f)
            : make_float4(0.0f, 0.0f, 0.0f, 0.0f);
    }
    __syncthreads();

    // Local step: absorb site SITE at digit stride S3 (digit c_y, y = SITE%6).
#define STEPL(SITE, S3, RD, WR) { \
    if (t < NG) { \
        int d_   = (t / (S3)) % 3; \
        int base = t - d_ * (S3); \
        float4 c0 = (RD)[base]; \
        float4 c1 = (RD)[base + (S3)]; \
        float4 c2 = (RD)[base + 2 * (S3)]; \
        const float4* Av = (const float4*)At + (SITE) * 27 + d_ * 9; \
        float r0 = dot3(c0, Av[0]) + dot3(c1, Av[1]) + dot3(c2, Av[2]); \
        float r1 = dot3(c0, Av[3]) + dot3(c1, Av[4]) + dot3(c2, Av[5]); \
        float r2 = dot3(c0, Av[6]) + dot3(c1, Av[7]) + dot3(c2, Av[8]); \
        (WR)[t] = make_float4(r0, r1, r2, 0.0f); \
    } \
    __syncthreads(); \
}

    // Transition step (y=0): contracts the shard digit c0 across the cluster.
    // out[part, g, hp] = sum_u state[u, g].x * A[a=u][o=part][h=0][hp]
#define STEPT(SITE, RD, WR) { \
    CLUSTER_BAR(); \
    if (t < NG) { \
        uint32_t la = smem_u32(RD) + (uint32_t)t * 16u; \
        float x0 = ld_cluster_f32(la, base_rank + 0); \
        float x1 = ld_cluster_f32(la, base_rank + 1); \
        float x2 = ld_cluster_f32(la, base_rank + 2); \
        const float* Af = At + (SITE) * ATF + part * 36; \
        float r0 = x0 * Af[0]  + x1 * Af[4]  + x2 * Af[8]; \
        float r1 = x0 * Af[12] + x1 * Af[16] + x2 * Af[20]; \
        float r2 = x0 * Af[24] + x1 * Af[28] + x2 * Af[32]; \
        (WR)[t] = make_float4(r0, r1, r2, 0.0f); \
    } \
    CLUSTER_BAR(); \
}

    // row 0 (site 0 folded into init); digit strides 3^(5-y) for y=1..5
    STEPL(1, 81, S0, S1)
    STEPL(2, 27, S1, S0)
    STEPL(3,  9, S0, S1)
    STEPL(4,  3, S1, S0)
    STEPL(5,  1, S0, S1)
    // row 1
    STEPT(6, S1, S0)
    STEPL(7,  81, S0, S1)
    STEPL(8,  27, S1, S0)
    STEPL(9,   9, S0, S1)
    STEPL(10,  3, S1, S0)
    STEPL(11,  1, S0, S1)
    // row 2
    STEPT(12, S1, S0)
    STEPL(13, 81, S0, S1)
    STEPL(14, 27, S1, S0)
    STEPL(15,  9, S0, S1)
    STEPL(16,  3, S1, S0)
    STEPL(17,  1, S0, S1)
#undef STEPL
#undef STEPT

    // Final state in S1. amplitude contribution of shard k:
    //   sum_g top[k, g].x * bottom[k, g].x  (h projected to boundary 0)
    CLUSTER_BAR();
    if (half == 0) {
        float s = 0.0f;
        if (t < NG) {
            uint32_t la = smem_u32(S1) + (uint32_t)t * 16u;
            s = S1[t].x * ld_cluster_f32(la, 3 + part);
        }
        #pragma unroll
        for (int o = 16; o; o >>= 1) s += __shfl_xor_sync(0xFFFFFFFFu, s, o);
        if ((t & 31) == 0) wred[t >> 5] = s;
        __syncthreads();
        if (t == 0) {
            float p = 0.0f;
            #pragma unroll
            for (int w = 0; w < 8; ++w) p += wred[w];
            st_cluster_f32(smem_u32(cred) + part * 4u, 0, p);
        }
    }
    CLUSTER_BAR();
    if (rank == 0 && t == 0)
        out[b] = cred[0] + cred[1] + cred[2];
}

extern "C" void kernel_launch(void* const* d_in, const int* in_sizes, int n_in,
                              void* d_out, int out_size) {
    const int*   xcfg = nullptr;
    const float* T    = nullptr;
    for (int i = 0; i < n_in; ++i) {
        if (in_sizes[i] == 576) xcfg = (const int*)d_in[i];
        else                    T    = (const float*)d_in[i];
    }
    float* out = (float*)d_out;
    peps_cluster_kernel<<<96, NTH>>>(xcfg, T, out);
}

// round 6
// speedup vs baseline: 1.6907x; 1.3273x over previous
#include <cuda_runtime.h>
#include <cstdint>

// PEPS 6x6, D=3, B=16 — quadrant decomposition, cluster of 4 CTAs per config.
// rank 0=TL (rows 0-2, cols 0-2), 1=TR (cols 5-3), 2=BL (rows 5-3), 3=BR.
// Each quadrant contracts its 9 sites locally (8 steps after init); state =
// 243 groups (digits a0..a4, strides 81,27,9,3,1) x float4 (moving bond in
// lanes .x/.y/.z). Digit roles evolve: a0,a1,a2 = column bonds; a3,a4 = open
// cut-edge bonds (rows 0,1 of the vertical cut); final lanes = cut row 2.
// Merge: M_half[v1(27),v2(27)] = sum_{9 groups x 3 lanes} QL[v1*9+j] . QR[v2*9+j];
// amplitude = sum_729 M_top * M_bot. Only 2 cluster barriers.
//
// Site tensor gather At[s][o][hp][a][lane] = T[u,d,l,r] with
//   u = bottom? o : a,  d = bottom? a : o   (vertical: contracted a, output o)
//   l = right? hp : lane, r = right? lane : hp (moving: in=lane, out=hp)
// Boundary bonds (lattice edges) are enforced by zero-propagation: contracted
// digits / lanes that correspond to edges are only nonzero at index 0.

#define NTH 256
#define ATF 108

__device__ __forceinline__ float dot3(float4 a, float4 b) {
    return a.x * b.x + a.y * b.y + a.z * b.z;
}

__device__ __forceinline__ uint32_t smem_u32(const void* p) {
    uint32_t a;
    asm("{ .reg .u64 t; cvta.to.shared.u64 t, %1; cvt.u32.u64 %0, t; }"
        : "=r"(a) : "l"(p));
    return a;
}

__device__ __forceinline__ float ld_cluster_f32(uint32_t laddr, uint32_t rank) {
    uint32_t r; float v;
    asm volatile("mapa.shared::cluster.u32 %0, %1, %2;" : "=r"(r) : "r"(laddr), "r"(rank));
    asm volatile("ld.shared::cluster.f32 %0, [%1];" : "=f"(v) : "r"(r) : "memory");
    return v;
}

__device__ __forceinline__ void st_cluster_f32(uint32_t laddr, uint32_t rank, float v) {
    uint32_t r;
    asm volatile("mapa.shared::cluster.u32 %0, %1, %2;" : "=r"(r) : "r"(laddr), "r"(rank));
    asm volatile("st.shared::cluster.f32 [%0], %1;" :: "r"(r), "f"(v) : "memory");
}

#define CLUSTER_BAR() do { \
    asm volatile("barrier.cluster.arrive.aligned;" ::: "memory"); \
    asm volatile("barrier.cluster.wait.aligned;"   ::: "memory"); \
} while (0)

__global__ __launch_bounds__(NTH, 1) __cluster_dims__(4, 1, 1)
void peps_quad_kernel(const int* __restrict__ xcfg,
                      const float* __restrict__ T,
                      float* __restrict__ out) {
    __shared__ float4 S0[243];
    __shared__ float4 S1[243];          // also peer-copy buffer in merge
    __shared__ float  At[9 * ATF];
    __shared__ float  M[729];           // my half's merged tensor (rank 0)
    __shared__ float  M2[729];          // bottom half's tensor (pushed by rank 2)
    __shared__ int    spins[36];
    __shared__ int    sOff[36];
    __shared__ float  red[8];

    const int t = threadIdx.x;
    const int b = blockIdx.x >> 2;
    uint32_t rank;
    asm("mov.u32 %0, %%cluster_ctarank;" : "=r"(rank));
    const int bottom = (int)(rank >> 1);
    const int right  = (int)(rank & 1);

    if (t < 36) spins[t] = xcfg[b * 36 + t];
    __syncthreads();
    if (t < 36) {
        int xx = t / 6, yy = t % 6;
        int p  = spins[t];
        int pu = (xx > 0) ? spins[t - 6] : 0;
        int pd = (xx < 5) ? spins[t + 6] : 0;
        int pl = (yy > 0) ? spins[t - 1] : 0;
        int pr = (yy < 5) ? spins[t + 1] : 0;
        sOff[t] = (((p * 2 + pu) * 2 + pd) * 2 + pl) * 2 + pr;
    }
    __syncthreads();

    // Gather my quadrant's 9 site tensors (processing order s = qrow*3 + qcol).
    for (int i = t; i < 9 * ATF; i += NTH) {
        int s = i / ATF, r = i - s * ATF;
        int o  = r / 36;  r -= o * 36;
        int hp = r / 12;  r -= hp * 12;
        int a  = r >> 2,  ln = r & 3;
        float v = 0.0f;
        if (ln < 3) {
            int x = bottom ? 5 - s / 3 : s / 3;
            int y = right  ? 5 - s % 3 : s % 3;
            int u  = bottom ? o : a;
            int d  = bottom ? a : o;
            int l  = right ? hp : ln;
            int rr = right ? ln : hp;
            int site = x * 6 + y;
            v = T[site * 2592 + (((u * 3 + d) * 3 + l) * 3 + rr) * 32 + sOff[site]];
        }
        At[i] = v;
    }
    __syncthreads();

    // Init = state after first site (s=0): digit a0 = vertical out, lanes =
    // moving-out bond hp; contracted (a=0, lane=0) are lattice edges.
    if (t < 243) {
        float4 v = make_float4(0.0f, 0.0f, 0.0f, 0.0f);
        if (t == 0 || t == 81 || t == 162) {
            int a0 = t / 81;
            v = make_float4(At[a0 * 36], At[a0 * 36 + 12], At[a0 * 36 + 24], 0.0f);
        }
        S0[t] = v;
    }
    __syncthreads();

    const float4* Atv = (const float4*)At;

    // Generic step: contract (digit @ stride S3, lanes), write (digit, lanes=hp).
#define STEPL(SITE, S3, RD, WR) { \
    if (t < 243) { \
        int d_   = (t / (S3)) % 3; \
        int base = t - d_ * (S3); \
        float4 c0 = (RD)[base]; \
        float4 c1 = (RD)[base + (S3)]; \
        float4 c2 = (RD)[base + 2 * (S3)]; \
        const float4* Av = Atv + (SITE) * 27 + d_ * 9; \
        float r0 = dot3(c0, Av[0]) + dot3(c1, Av[1]) + dot3(c2, Av[2]); \
        float r1 = dot3(c0, Av[3]) + dot3(c1, Av[4]) + dot3(c2, Av[5]); \
        float r2 = dot3(c0, Av[6]) + dot3(c1, Av[7]) + dot3(c2, Av[8]); \
        (WR)[t] = make_float4(r0, r1, r2, 0.0f); \
    } \
    __syncthreads(); \
}

    // Row-end step, r -> a3: out(a0,a1,d,r,a4) = sum_u in(a0,a1,u,0,a4).dot(A[d][r][u])
#define STEPC3(SITE, RD, WR) { \
    if (t < 243) { \
        int rr_  = t % 27; \
        int d_   = rr_ / 9; \
        int r_   = (rr_ / 3) % 3; \
        int base = (t / 27) * 27 + (rr_ % 3); \
        const float4* Av = Atv + (SITE) * 27 + d_ * 9 + r_ * 3; \
        float s_ = dot3((RD)[base], Av[0]) + dot3((RD)[base + 9], Av[1]) \
                 + dot3((RD)[base + 18], Av[2]); \
        (WR)[t] = make_float4(s_, 0.0f, 0.0f, 0.0f); \
    } \
    __syncthreads(); \
}

    // Row-end step, r -> a4: out(a0,a1,d,a3,r) = sum_u in(a0,a1,u,a3,0).dot(A[d][r][u])
#define STEPC4(SITE, RD, WR) { \
    if (t < 243) { \
        int d_   = (t / 9) % 3; \
        int r_   = t % 3; \
        int base = (t / 27) * 27 + ((t / 3) % 3) * 3; \
        const float4* Av = Atv + (SITE) * 27 + d_ * 9 + r_ * 3; \
        float s_ = dot3((RD)[base], Av[0]) + dot3((RD)[base + 9], Av[1]) \
                 + dot3((RD)[base + 18], Av[2]); \
        (WR)[t] = make_float4(s_, 0.0f, 0.0f, 0.0f); \
    } \
    __syncthreads(); \
}

    STEPL (1, 27, S0, S1)   // (q0,1): contract a1(=edge,0-only) + lane
    STEPC3(2,     S1, S0)   // (q0,2): open cut bond row0 -> a3
    STEPL (3, 81, S0, S1)   // (q1,0): contract a0 + lane(edge, .x-only)
    STEPL (4, 27, S1, S0)   // (q1,1)
    STEPC4(5,     S0, S1)   // (q1,2): open cut bond row1 -> a4
    STEPL (6, 81, S1, S0)   // (q2,0)
    STEPL (7, 27, S0, S1)   // (q2,1)
    STEPL (8,  9, S1, S0)   // (q2,2): cut bond row2 -> lanes. Final in S0.
#undef STEPL
#undef STEPC3
#undef STEPC4

    CLUSTER_BAR();

    // Ranks 0 (top) and 2 (bottom): pull peer quadrant (rank+1) and merge.
    if (right == 0) {
        float* S1f = (float*)S1;
        uint32_t s0a = smem_u32(S0);
        for (int i = t; i < 972; i += NTH)
            S1f[i] = ld_cluster_f32(s0a + (uint32_t)i * 4u, rank + 1);
        __syncthreads();
        uint32_t m2a = smem_u32(M2);
        for (int v = t; v < 729; v += NTH) {
            int v1 = v / 27, v2 = v - 27 * (v / 27);
            const float4* L = S0 + v1 * 9;
            const float4* R = S1 + v2 * 9;
            float s = 0.0f;
            #pragma unroll
            for (int j = 0; j < 9; ++j) s += dot3(L[j], R[j]);
            if (bottom) st_cluster_f32(m2a + (uint32_t)v * 4u, 0, s);
            else        M[v] = s;
        }
    }
    CLUSTER_BAR();

    if (rank == 0) {
        float s = 0.0f;
        for (int v = t; v < 729; v += NTH) s += M[v] * M2[v];
        #pragma unroll
        for (int o = 16; o; o >>= 1) s += __shfl_xor_sync(0xFFFFFFFFu, s, o);
        if ((t & 31) == 0) red[t >> 5] = s;
        __syncthreads();
        if (t == 0) {
            float tt = 0.0f;
            #pragma unroll
            for (int w = 0; w < 8; ++w) tt += red[w];
            out[b] = tt;
        }
    }
}

extern "C" void kernel_launch(void* const* d_in, const int* in_sizes, int n_in,
                              void* d_out, int out_size) {
    const int*   xcfg = nullptr;
    const float* T    = nullptr;
    for (int i = 0; i < n_in; ++i) {
        if (in_sizes[i] == 576) xcfg = (const int*)d_in[i];
        else                    T    = (const float*)d_in[i];
    }
    float* out = (float*)d_out;
    peps_quad_kernel<<<64, NTH>>>(xcfg, T, out);
}